// round 2
// baseline (speedup 1.0000x reference)
#include <cuda_runtime.h>
#include <math.h>

#define SS   2048
#define DD   1024
#define NL   4
#define NH   16
#define HDIM 64
#define NV   50257
#define DMLP 4096

// ---------------- scratch (device globals: allocation-free) ----------------
__device__ float g_x[SS * DD];
__device__ float g_h[SS * DD];
__device__ float g_q[SS * DD];
__device__ float g_k[SS * DD];
__device__ float g_v[SS * DD];
__device__ float g_mlp[SS * DMLP];
__device__ float g_scores[(size_t)NH * SS * SS];   // 256 MB

// ---------------- embedding gather (ids are int32: JAX x64 is disabled) ----
__global__ void embed_kernel(const int* __restrict__ ids,
                             const float* __restrict__ emb,
                             float* __restrict__ x) {
    int t = blockIdx.x;
    int id = ids[t];
    if (id < 0) id = 0;
    if (id >= NV) id = NV - 1;
    const float* src = emb + (size_t)id * DD;
    float* dst = x + (size_t)t * DD;
    for (int d = threadIdx.x; d < DD; d += blockDim.x) dst[d] = src[d];
}

// ---------------- layernorm (two-pass, block per row) ----------------
__global__ void layernorm_kernel(const float* __restrict__ x,
                                 const float* __restrict__ g,
                                 const float* __restrict__ b,
                                 float* __restrict__ out) {
    __shared__ float red[256];
    int row = blockIdx.x;
    const float* xr = x + (size_t)row * DD;
    float s = 0.f;
    for (int d = threadIdx.x; d < DD; d += 256) s += xr[d];
    red[threadIdx.x] = s;
    __syncthreads();
    for (int o = 128; o > 0; o >>= 1) {
        if (threadIdx.x < o) red[threadIdx.x] += red[threadIdx.x + o];
        __syncthreads();
    }
    float mean = red[0] * (1.f / DD);
    __syncthreads();
    float v = 0.f;
    for (int d = threadIdx.x; d < DD; d += 256) {
        float t = xr[d] - mean;
        v += t * t;
    }
    red[threadIdx.x] = v;
    __syncthreads();
    for (int o = 128; o > 0; o >>= 1) {
        if (threadIdx.x < o) red[threadIdx.x] += red[threadIdx.x + o];
        __syncthreads();
    }
    float inv = rsqrtf(red[0] * (1.f / DD) + 1e-5f);
    float* orow = out + (size_t)row * DD;
    for (int d = threadIdx.x; d < DD; d += 256)
        orow[d] = (xr[d] - mean) * inv * g[d] + b[d];
}

// ---------------- RoPE on q and k in-place ----------------
__global__ void rope_kernel(float* __restrict__ q, float* __restrict__ k) {
    int idx = blockIdx.x * blockDim.x + threadIdx.x;   // S*H*32 threads
    int i = idx & 31;
    int rest = idx >> 5;
    int h = rest & (NH - 1);
    int t = rest >> 4;
    if (t >= SS) return;
    float inv_freq = powf(10000.f, -(float)i / 32.f);
    float ang = (float)t * inv_freq;
    float c = cosf(ang), s = sinf(ang);
    size_t base = (size_t)t * DD + h * HDIM;
    float x1 = q[base + i], x2 = q[base + i + 32];
    q[base + i]      = x1 * c - x2 * s;
    q[base + i + 32] = x2 * c + x1 * s;
    float y1 = k[base + i], y2 = k[base + i + 32];
    k[base + i]      = y1 * c - y2 * s;
    k[base + i + 32] = y2 * c + y1 * s;
}

// ---------------- causal softmax (block per (row, head)) ----------------
__global__ void softmax_kernel(float* __restrict__ scores) {
    __shared__ float red[256];
    int s = blockIdx.x, h = blockIdx.y;
    float* row = scores + ((size_t)h * SS + s) * SS;
    int valid = s + 1;
    float m = -1e30f;
    for (int j = threadIdx.x; j < valid; j += 256) m = fmaxf(m, row[j]);
    red[threadIdx.x] = m;
    __syncthreads();
    for (int o = 128; o > 0; o >>= 1) {
        if (threadIdx.x < o) red[threadIdx.x] = fmaxf(red[threadIdx.x], red[threadIdx.x + o]);
        __syncthreads();
    }
    m = red[0];
    __syncthreads();
    float sum = 0.f;
    for (int j = threadIdx.x; j < valid; j += 256) {
        float e = expf(row[j] - m);
        row[j] = e;
        sum += e;
    }
    red[threadIdx.x] = sum;
    __syncthreads();
    for (int o = 128; o > 0; o >>= 1) {
        if (threadIdx.x < o) red[threadIdx.x] += red[threadIdx.x + o];
        __syncthreads();
    }
    float invs = 1.f / red[0];
    for (int j = threadIdx.x; j < SS; j += 256)
        row[j] = (j < valid) ? row[j] * invs : 0.f;
}

// ---------------- batched SGEMM 128x128x8, fused epilogue ----------------
// C = alpha * A*op(B) [+ bias] [+ res] ; optional exact GELU.
// TB=false: B is (K x N) row-major, access B[k*ldb + n]
// TB=true:  B is (N x K) row-major, access B[n*ldb + k]
// Batch via blockIdx.z with element strides.
template <bool TB>
__global__ void __launch_bounds__(256)
sgemm_kernel(const float* __restrict__ A, int lda, long long strideA,
             const float* __restrict__ B, int ldb, long long strideB,
             float* __restrict__ C, int ldc, long long strideC,
             int M, int N, int K, float alpha,
             const float* __restrict__ bias,
             const float* __restrict__ res,
             int do_gelu) {
    __shared__ float As[8][128];
    __shared__ float Bs[8][129];

    int z = blockIdx.z;
    A += (size_t)z * strideA;
    B += (size_t)z * strideB;
    C += (size_t)z * strideC;
    if (res) res += (size_t)z * strideC;

    int row0 = blockIdx.y * 128;
    int col0 = blockIdx.x * 128;
    int tid = threadIdx.x;
    int tx = tid & 15;        // col group
    int ty = tid >> 4;        // row group

    float acc[8][8];
#pragma unroll
    for (int i = 0; i < 8; i++)
#pragma unroll
        for (int j = 0; j < 8; j++) acc[i][j] = 0.f;

    for (int k0 = 0; k0 < K; k0 += 8) {
        // load A tile 128x8 -> As[k][m]
#pragma unroll
        for (int it = 0; it < 4; it++) {
            int lin = tid + it * 256;
            int r = lin >> 3, c = lin & 7;
            int gr = row0 + r;
            As[c][r] = (gr < M) ? A[(size_t)gr * lda + (k0 + c)] : 0.f;
        }
        // load B tile -> Bs[k][n]
#pragma unroll
        for (int it = 0; it < 4; it++) {
            int lin = tid + it * 256;
            if (TB) {
                int n = lin >> 3, c = lin & 7;
                int gn = col0 + n;
                Bs[c][n] = (gn < N) ? B[(size_t)gn * ldb + (k0 + c)] : 0.f;
            } else {
                int c = lin >> 7, n = lin & 127;
                int gn = col0 + n;
                Bs[c][n] = (gn < N) ? B[(size_t)(k0 + c) * ldb + gn] : 0.f;
            }
        }
        __syncthreads();
#pragma unroll
        for (int kk = 0; kk < 8; kk++) {
            float a[8], b[8];
#pragma unroll
            for (int i = 0; i < 8; i++) a[i] = As[kk][ty * 8 + i];
#pragma unroll
            for (int j = 0; j < 8; j++) b[j] = Bs[kk][tx * 8 + j];
#pragma unroll
            for (int i = 0; i < 8; i++)
#pragma unroll
                for (int j = 0; j < 8; j++) acc[i][j] += a[i] * b[j];
        }
        __syncthreads();
    }

#pragma unroll
    for (int i = 0; i < 8; i++) {
        int gr = row0 + ty * 8 + i;
        if (gr >= M) continue;
#pragma unroll
        for (int j = 0; j < 8; j++) {
            int gc = col0 + tx * 8 + j;
            if (gc >= N) continue;
            float v = alpha * acc[i][j];
            if (bias) v += bias[gc];
            if (res) v += res[(size_t)gr * ldc + gc];
            if (do_gelu) v = 0.5f * v * (1.f + erff(v * 0.70710678118654752f));
            C[(size_t)gr * ldc + gc] = v;
        }
    }
}

// ---------------- host orchestration ----------------
extern "C" void kernel_launch(void* const* d_in, const int* in_sizes, int n_in,
                              void* d_out, int out_size) {
    const int* ids   = (const int*)d_in[0];      // int32: JAX x64 disabled
    const float* emb  = (const float*)d_in[1];
    const float* Wq   = (const float*)d_in[2];
    const float* Wk   = (const float*)d_in[3];
    const float* Wv   = (const float*)d_in[4];
    const float* Wo   = (const float*)d_in[5];
    const float* ln1g = (const float*)d_in[6];
    const float* ln1b = (const float*)d_in[7];
    const float* ln2g = (const float*)d_in[8];
    const float* ln2b = (const float*)d_in[9];
    const float* W1   = (const float*)d_in[10];
    const float* b1   = (const float*)d_in[11];
    const float* W2   = (const float*)d_in[12];
    const float* b2   = (const float*)d_in[13];
    const float* lnfg = (const float*)d_in[14];
    const float* lnfb = (const float*)d_in[15];
    float* out = (float*)d_out;

    float *x, *h, *q, *k, *v, *mlp, *sc;
    cudaGetSymbolAddress((void**)&x,   g_x);
    cudaGetSymbolAddress((void**)&h,   g_h);
    cudaGetSymbolAddress((void**)&q,   g_q);
    cudaGetSymbolAddress((void**)&k,   g_k);
    cudaGetSymbolAddress((void**)&v,   g_v);
    cudaGetSymbolAddress((void**)&mlp, g_mlp);
    cudaGetSymbolAddress((void**)&sc,  g_scores);

    embed_kernel<<<SS, 256>>>(ids, emb, x);

    for (int l = 0; l < NL; l++) {
        const size_t wofs = (size_t)l * DD * DD;
        layernorm_kernel<<<SS, 256>>>(x, ln1g + l * DD, ln1b + l * DD, h);

        dim3 gp(DD / 128, SS / 128, 1);
        sgemm_kernel<false><<<gp, 256>>>(h, DD, 0, Wq + wofs, DD, 0, q, DD, 0,
                                         SS, DD, DD, 1.f, nullptr, nullptr, 0);
        sgemm_kernel<false><<<gp, 256>>>(h, DD, 0, Wk + wofs, DD, 0, k, DD, 0,
                                         SS, DD, DD, 1.f, nullptr, nullptr, 0);
        sgemm_kernel<false><<<gp, 256>>>(h, DD, 0, Wv + wofs, DD, 0, v, DD, 0,
                                         SS, DD, DD, 1.f, nullptr, nullptr, 0);

        rope_kernel<<<(SS * NH * 32 + 255) / 256, 256>>>(q, k);

        // scores[h] = 1/8 * q_h @ k_h^T   (batched over heads)
        dim3 gs(SS / 128, SS / 128, NH);
        sgemm_kernel<true><<<gs, 256>>>(q, DD, HDIM, k, DD, HDIM,
                                        sc, SS, (long long)SS * SS,
                                        SS, SS, HDIM, 0.125f, nullptr, nullptr, 0);

        softmax_kernel<<<dim3(SS, NH), 256>>>(sc);

        // attn_out[h] = softmax @ v_h  -> concat into h
        dim3 ga(1, SS / 128, NH);
        sgemm_kernel<false><<<ga, 256>>>(sc, SS, (long long)SS * SS, v, DD, HDIM,
                                         h, DD, HDIM,
                                         SS, HDIM, SS, 1.f, nullptr, nullptr, 0);

        // x = x + attn @ Wo
        dim3 go(DD / 128, SS / 128, 1);
        sgemm_kernel<false><<<go, 256>>>(h, DD, 0, Wo + wofs, DD, 0, x, DD, 0,
                                         SS, DD, DD, 1.f, nullptr, x, 0);

        layernorm_kernel<<<SS, 256>>>(x, ln2g + l * DD, ln2b + l * DD, h);

        // mlp = gelu(h @ W1 + b1)
        dim3 g1(DMLP / 128, SS / 128, 1);
        sgemm_kernel<false><<<g1, 256>>>(h, DD, 0, W1 + (size_t)l * DD * DMLP, DMLP, 0,
                                         mlp, DMLP, 0,
                                         SS, DMLP, DD, 1.f, b1 + (size_t)l * DMLP, nullptr, 1);

        // x = x + mlp @ W2 + b2
        dim3 g2(DD / 128, SS / 128, 1);
        sgemm_kernel<false><<<g2, 256>>>(mlp, DMLP, 0, W2 + (size_t)l * DMLP * DD, DD, 0,
                                         x, DD, 0,
                                         SS, DD, DMLP, 1.f, b2 + (size_t)l * DD, x, 0);
    }

    layernorm_kernel<<<SS, 256>>>(x, lnfg, lnfb, h);

    // logits = h @ emb^T
    dim3 gl((NV + 127) / 128, SS / 128, 1);
    sgemm_kernel<true><<<gl, 256>>>(h, DD, 0, emb, DD, 0, out, NV, 0,
                                    SS, NV, DD, 1.f, nullptr, nullptr, 0);
}

// round 3
// speedup vs baseline: 4.0381x; 4.0381x over previous
#include <cuda_runtime.h>
#include <math.h>

#define SS   2048
#define DD   1024
#define NL   4
#define NH   16
#define HDIM 64
#define NV   50257
#define DMLP 4096

// ---------------- scratch (device globals: allocation-free) ----------------
__device__ float g_x[SS * DD];
__device__ float g_h[SS * DD];
__device__ float g_q[SS * DD];
__device__ float g_k[SS * DD];
__device__ float g_v[SS * DD];
__device__ float g_mlp[SS * DMLP];
__device__ float g_scores[(size_t)NH * SS * SS];   // 256 MB

// ---------------- embedding gather (ids are int32) ----------------
__global__ void embed_kernel(const int* __restrict__ ids,
                             const float* __restrict__ emb,
                             float* __restrict__ x) {
    int t = blockIdx.x;
    int id = ids[t];
    if (id < 0) id = 0;
    if (id >= NV) id = NV - 1;
    const float* src = emb + (size_t)id * DD;
    float* dst = x + (size_t)t * DD;
    for (int d = threadIdx.x; d < DD; d += blockDim.x) dst[d] = src[d];
}

// ---------------- layernorm ----------------
__global__ void layernorm_kernel(const float* __restrict__ x,
                                 const float* __restrict__ g,
                                 const float* __restrict__ b,
                                 float* __restrict__ out) {
    __shared__ float red[256];
    int row = blockIdx.x;
    const float* xr = x + (size_t)row * DD;
    float s = 0.f;
    for (int d = threadIdx.x; d < DD; d += 256) s += xr[d];
    red[threadIdx.x] = s;
    __syncthreads();
    for (int o = 128; o > 0; o >>= 1) {
        if (threadIdx.x < o) red[threadIdx.x] += red[threadIdx.x + o];
        __syncthreads();
    }
    float mean = red[0] * (1.f / DD);
    __syncthreads();
    float v = 0.f;
    for (int d = threadIdx.x; d < DD; d += 256) {
        float t = xr[d] - mean;
        v += t * t;
    }
    red[threadIdx.x] = v;
    __syncthreads();
    for (int o = 128; o > 0; o >>= 1) {
        if (threadIdx.x < o) red[threadIdx.x] += red[threadIdx.x + o];
        __syncthreads();
    }
    float inv = rsqrtf(red[0] * (1.f / DD) + 1e-5f);
    float* orow = out + (size_t)row * DD;
    for (int d = threadIdx.x; d < DD; d += 256)
        orow[d] = (xr[d] - mean) * inv * g[d] + b[d];
}

// ---------------- RoPE on q and k in-place ----------------
__global__ void rope_kernel(float* __restrict__ q, float* __restrict__ k) {
    int idx = blockIdx.x * blockDim.x + threadIdx.x;
    int i = idx & 31;
    int rest = idx >> 5;
    int h = rest & (NH - 1);
    int t = rest >> 4;
    if (t >= SS) return;
    float inv_freq = powf(10000.f, -(float)i / 32.f);
    float ang = (float)t * inv_freq;
    float c = cosf(ang), s = sinf(ang);
    size_t base = (size_t)t * DD + h * HDIM;
    float x1 = q[base + i], x2 = q[base + i + 32];
    q[base + i]      = x1 * c - x2 * s;
    q[base + i + 32] = x2 * c + x1 * s;
    float y1 = k[base + i], y2 = k[base + i + 32];
    k[base + i]      = y1 * c - y2 * s;
    k[base + i + 32] = y2 * c + y1 * s;
}

// ---------------- causal softmax ----------------
__global__ void softmax_kernel(float* __restrict__ scores) {
    __shared__ float red[256];
    int s = blockIdx.x, h = blockIdx.y;
    float* row = scores + ((size_t)h * SS + s) * SS;
    int valid = s + 1;
    float m = -1e30f;
    for (int j = threadIdx.x; j < valid; j += 256) m = fmaxf(m, row[j]);
    red[threadIdx.x] = m;
    __syncthreads();
    for (int o = 128; o > 0; o >>= 1) {
        if (threadIdx.x < o) red[threadIdx.x] = fmaxf(red[threadIdx.x], red[threadIdx.x + o]);
        __syncthreads();
    }
    m = red[0];
    __syncthreads();
    float sum = 0.f;
    for (int j = threadIdx.x; j < valid; j += 256) {
        float e = expf(row[j] - m);
        row[j] = e;
        sum += e;
    }
    red[threadIdx.x] = sum;
    __syncthreads();
    for (int o = 128; o > 0; o >>= 1) {
        if (threadIdx.x < o) red[threadIdx.x] += red[threadIdx.x + o];
        __syncthreads();
    }
    float invs = 1.f / red[0];
    for (int j = threadIdx.x; j < SS; j += 256)
        row[j] = (j < valid) ? row[j] * invs : 0.f;
}

// ================= TF32 tensor-core GEMM =================
// C = alpha*A*op(B) [+bias] [+res] [gelu]; 128x128 block, BK=16, double buffered.
// TB=false: B is KxN row-major. TB=true: B is NxK row-major.
// causal: skip blocks fully above diagonal. kcap: limit K to row0+128.
#define BMT 128
#define BNT 128
#define BKT 16
#define APITCH 20      // pitch % 32 == 4 -> conflict-free m16k8 frag loads
#define BPN   136      // pitch % 32 == 8 -> conflict-free k8n8 frag loads
#define BPT   20

__device__ __forceinline__ unsigned f2tf(float f) {
    unsigned u;
    asm("cvt.rna.tf32.f32 %0, %1;" : "=r"(u) : "f"(f));
    return u;
}

__device__ __forceinline__ void mma_tf32(float c[4], unsigned a0, unsigned a1,
                                         unsigned a2, unsigned a3,
                                         unsigned b0, unsigned b1) {
    asm volatile(
        "mma.sync.aligned.m16n8k8.row.col.f32.tf32.tf32.f32 "
        "{%0,%1,%2,%3}, {%4,%5,%6,%7}, {%8,%9}, {%0,%1,%2,%3};"
        : "+f"(c[0]), "+f"(c[1]), "+f"(c[2]), "+f"(c[3])
        : "r"(a0), "r"(a1), "r"(a2), "r"(a3), "r"(b0), "r"(b1));
}

template <bool TB>
__global__ void __launch_bounds__(256)
tgemm_kernel(const float* __restrict__ A, int lda, long long strideA,
             const float* __restrict__ B, int ldb, long long strideB,
             float* __restrict__ C, int ldc, long long strideC,
             int M, int N, int K, float alpha,
             const float* __restrict__ bias,
             const float* __restrict__ res,
             int do_gelu, int causal, int kcap) {
    __shared__ float As[2][BMT * APITCH];
    __shared__ float Bs[2][TB ? (BNT * BPT) : (BKT * BPN)];

    int z = blockIdx.z;
    A += (size_t)z * strideA;
    B += (size_t)z * strideB;
    C += (size_t)z * strideC;
    if (res) res += (size_t)z * strideC;

    int row0 = blockIdx.y * BMT;
    int col0 = blockIdx.x * BNT;
    if (causal && col0 >= row0 + BMT) return;

    int Keff = K;
    if (kcap) { int kc = row0 + BMT; Keff = (K < kc) ? K : kc; }
    int nk = Keff / BKT;

    int tid = threadIdx.x;
    int lane = tid & 31, warp = tid >> 5;
    int wm = warp >> 2, wn = warp & 3;       // 2 x 4 warp grid
    int l4 = lane & 3, l28 = lane >> 2;
    int mbase = wm * 64;
    int nbase = wn * 32;

    float acc[4][4][4];
#pragma unroll
    for (int mt = 0; mt < 4; mt++)
#pragma unroll
        for (int nt = 0; nt < 4; nt++)
#pragma unroll
            for (int c = 0; c < 4; c++) acc[mt][nt][c] = 0.f;

    float4 ra[2], rb[2];

    // ---- stage-0 load + store ----
    {
        int k0 = 0;
#pragma unroll
        for (int i = 0; i < 2; i++) {
            int lin = i * 256 + tid;
            int m = lin >> 2, f4 = lin & 3;
            ra[i] = *(const float4*)(A + (size_t)(row0 + m) * lda + k0 + f4 * 4);
        }
#pragma unroll
        for (int i = 0; i < 2; i++) {
            int lin = i * 256 + tid;
            if (TB) {
                int n = lin >> 2, f4 = lin & 3;
                int gn = col0 + n;
                rb[i] = (gn < N) ? *(const float4*)(B + (size_t)gn * ldb + k0 + f4 * 4)
                                 : make_float4(0.f, 0.f, 0.f, 0.f);
            } else {
                int kk = lin >> 5, f4 = lin & 31;
                int gn = col0 + f4 * 4;
                rb[i] = (gn < N) ? *(const float4*)(B + (size_t)(k0 + kk) * ldb + gn)
                                 : make_float4(0.f, 0.f, 0.f, 0.f);
            }
        }
#pragma unroll
        for (int i = 0; i < 2; i++) {
            int lin = i * 256 + tid;
            int m = lin >> 2, f4 = lin & 3;
            float4 t;
            t.x = __uint_as_float(f2tf(ra[i].x));
            t.y = __uint_as_float(f2tf(ra[i].y));
            t.z = __uint_as_float(f2tf(ra[i].z));
            t.w = __uint_as_float(f2tf(ra[i].w));
            *(float4*)&As[0][m * APITCH + f4 * 4] = t;
        }
#pragma unroll
        for (int i = 0; i < 2; i++) {
            int lin = i * 256 + tid;
            float4 t;
            t.x = __uint_as_float(f2tf(rb[i].x));
            t.y = __uint_as_float(f2tf(rb[i].y));
            t.z = __uint_as_float(f2tf(rb[i].z));
            t.w = __uint_as_float(f2tf(rb[i].w));
            if (TB) {
                int n = lin >> 2, f4 = lin & 3;
                *(float4*)&Bs[0][n * BPT + f4 * 4] = t;
            } else {
                int kk = lin >> 5, f4 = lin & 31;
                *(float4*)&Bs[0][kk * BPN + f4 * 4] = t;
            }
        }
    }
    __syncthreads();

    for (int ks = 0; ks < nk; ks++) {
        int cur = ks & 1, nxt = cur ^ 1;
        bool more = (ks + 1) < nk;
        if (more) {
            int k0 = (ks + 1) * BKT;
#pragma unroll
            for (int i = 0; i < 2; i++) {
                int lin = i * 256 + tid;
                int m = lin >> 2, f4 = lin & 3;
                ra[i] = *(const float4*)(A + (size_t)(row0 + m) * lda + k0 + f4 * 4);
            }
#pragma unroll
            for (int i = 0; i < 2; i++) {
                int lin = i * 256 + tid;
                if (TB) {
                    int n = lin >> 2, f4 = lin & 3;
                    int gn = col0 + n;
                    rb[i] = (gn < N) ? *(const float4*)(B + (size_t)gn * ldb + k0 + f4 * 4)
                                     : make_float4(0.f, 0.f, 0.f, 0.f);
                } else {
                    int kk = lin >> 5, f4 = lin & 31;
                    int gn = col0 + f4 * 4;
                    rb[i] = (gn < N) ? *(const float4*)(B + (size_t)(k0 + kk) * ldb + gn)
                                     : make_float4(0.f, 0.f, 0.f, 0.f);
                }
            }
        }

        // ---- compute on cur ----
#pragma unroll
        for (int kk8 = 0; kk8 < 2; kk8++) {
            int kb = kk8 * 8;
            unsigned af[4][4];
#pragma unroll
            for (int mt = 0; mt < 4; mt++) {
                int mrow = mbase + mt * 16 + l28;
                af[mt][0] = __float_as_uint(As[cur][mrow * APITCH + kb + l4]);
                af[mt][1] = __float_as_uint(As[cur][(mrow + 8) * APITCH + kb + l4]);
                af[mt][2] = __float_as_uint(As[cur][mrow * APITCH + kb + l4 + 4]);
                af[mt][3] = __float_as_uint(As[cur][(mrow + 8) * APITCH + kb + l4 + 4]);
            }
            unsigned bf[4][2];
#pragma unroll
            for (int nt = 0; nt < 4; nt++) {
                int ncol = nbase + nt * 8 + l28;
                if (TB) {
                    bf[nt][0] = __float_as_uint(Bs[cur][ncol * BPT + kb + l4]);
                    bf[nt][1] = __float_as_uint(Bs[cur][ncol * BPT + kb + l4 + 4]);
                } else {
                    bf[nt][0] = __float_as_uint(Bs[cur][(kb + l4) * BPN + ncol]);
                    bf[nt][1] = __float_as_uint(Bs[cur][(kb + l4 + 4) * BPN + ncol]);
                }
            }
#pragma unroll
            for (int mt = 0; mt < 4; mt++)
#pragma unroll
                for (int nt = 0; nt < 4; nt++)
                    mma_tf32(acc[mt][nt], af[mt][0], af[mt][1], af[mt][2], af[mt][3],
                             bf[nt][0], bf[nt][1]);
        }

        if (more) {
#pragma unroll
            for (int i = 0; i < 2; i++) {
                int lin = i * 256 + tid;
                int m = lin >> 2, f4 = lin & 3;
                float4 t;
                t.x = __uint_as_float(f2tf(ra[i].x));
                t.y = __uint_as_float(f2tf(ra[i].y));
                t.z = __uint_as_float(f2tf(ra[i].z));
                t.w = __uint_as_float(f2tf(ra[i].w));
                *(float4*)&As[nxt][m * APITCH + f4 * 4] = t;
            }
#pragma unroll
            for (int i = 0; i < 2; i++) {
                int lin = i * 256 + tid;
                float4 t;
                t.x = __uint_as_float(f2tf(rb[i].x));
                t.y = __uint_as_float(f2tf(rb[i].y));
                t.z = __uint_as_float(f2tf(rb[i].z));
                t.w = __uint_as_float(f2tf(rb[i].w));
                if (TB) {
                    int n = lin >> 2, f4 = lin & 3;
                    *(float4*)&Bs[nxt][n * BPT + f4 * 4] = t;
                } else {
                    int kk = lin >> 5, f4 = lin & 31;
                    *(float4*)&Bs[nxt][kk * BPN + f4 * 4] = t;
                }
            }
        }
        __syncthreads();
    }

    // ---- epilogue ----
#pragma unroll
    for (int mt = 0; mt < 4; mt++) {
#pragma unroll
        for (int nt = 0; nt < 4; nt++) {
#pragma unroll
            for (int c = 0; c < 4; c++) {
                int gr = row0 + mbase + mt * 16 + l28 + ((c >= 2) ? 8 : 0);
                int gc = col0 + nbase + nt * 8 + l4 * 2 + (c & 1);
                if (gc >= N) continue;
                float v = alpha * acc[mt][nt][c];
                if (bias) v += bias[gc];
                if (res) v += res[(size_t)gr * ldc + gc];
                if (do_gelu) v = 0.5f * v * (1.f + erff(v * 0.70710678118654752f));
                C[(size_t)gr * ldc + gc] = v;
            }
        }
    }
}

// ---------------- host orchestration ----------------
extern "C" void kernel_launch(void* const* d_in, const int* in_sizes, int n_in,
                              void* d_out, int out_size) {
    const int*   ids  = (const int*)d_in[0];
    const float* emb  = (const float*)d_in[1];
    const float* Wq   = (const float*)d_in[2];
    const float* Wk   = (const float*)d_in[3];
    const float* Wv   = (const float*)d_in[4];
    const float* Wo   = (const float*)d_in[5];
    const float* ln1g = (const float*)d_in[6];
    const float* ln1b = (const float*)d_in[7];
    const float* ln2g = (const float*)d_in[8];
    const float* ln2b = (const float*)d_in[9];
    const float* W1   = (const float*)d_in[10];
    const float* b1   = (const float*)d_in[11];
    const float* W2   = (const float*)d_in[12];
    const float* b2   = (const float*)d_in[13];
    const float* lnfg = (const float*)d_in[14];
    const float* lnfb = (const float*)d_in[15];
    float* out = (float*)d_out;

    float *x, *h, *q, *k, *v, *mlp, *sc;
    cudaGetSymbolAddress((void**)&x,   g_x);
    cudaGetSymbolAddress((void**)&h,   g_h);
    cudaGetSymbolAddress((void**)&q,   g_q);
    cudaGetSymbolAddress((void**)&k,   g_k);
    cudaGetSymbolAddress((void**)&v,   g_v);
    cudaGetSymbolAddress((void**)&mlp, g_mlp);
    cudaGetSymbolAddress((void**)&sc,  g_scores);

    embed_kernel<<<SS, 256>>>(ids, emb, x);

    for (int l = 0; l < NL; l++) {
        const size_t wofs = (size_t)l * DD * DD;
        layernorm_kernel<<<SS, 256>>>(x, ln1g + l * DD, ln1b + l * DD, h);

        dim3 gp(DD / 128, SS / 128, 1);
        tgemm_kernel<false><<<gp, 256>>>(h, DD, 0, Wq + wofs, DD, 0, q, DD, 0,
                                         SS, DD, DD, 1.f, nullptr, nullptr, 0, 0, 0);
        tgemm_kernel<false><<<gp, 256>>>(h, DD, 0, Wk + wofs, DD, 0, k, DD, 0,
                                         SS, DD, DD, 1.f, nullptr, nullptr, 0, 0, 0);
        tgemm_kernel<false><<<gp, 256>>>(h, DD, 0, Wv + wofs, DD, 0, v, DD, 0,
                                         SS, DD, DD, 1.f, nullptr, nullptr, 0, 0, 0);

        rope_kernel<<<(SS * NH * 32 + 255) / 256, 256>>>(q, k);

        // scores[h] = 1/8 * q_h @ k_h^T  (causal: skip blocks above diagonal)
        dim3 gs(SS / 128, SS / 128, NH);
        tgemm_kernel<true><<<gs, 256>>>(q, DD, HDIM, k, DD, HDIM,
                                        sc, SS, (long long)SS * SS,
                                        SS, SS, HDIM, 0.125f, nullptr, nullptr, 0, 1, 0);

        softmax_kernel<<<dim3(SS, NH), 256>>>(sc);

        // attn_out[h] = softmax @ v_h   (kcap: K limited to row0+128)
        dim3 ga(1, SS / 128, NH);
        tgemm_kernel<false><<<ga, 256>>>(sc, SS, (long long)SS * SS, v, DD, HDIM,
                                         h, DD, HDIM,
                                         SS, HDIM, SS, 1.f, nullptr, nullptr, 0, 0, 1);

        // x = x + attn @ Wo
        dim3 go(DD / 128, SS / 128, 1);
        tgemm_kernel<false><<<go, 256>>>(h, DD, 0, Wo + wofs, DD, 0, x, DD, 0,
                                         SS, DD, DD, 1.f, nullptr, x, 0, 0, 0);

        layernorm_kernel<<<SS, 256>>>(x, ln2g + l * DD, ln2b + l * DD, h);

        // mlp = gelu(h @ W1 + b1)
        dim3 g1(DMLP / 128, SS / 128, 1);
        tgemm_kernel<false><<<g1, 256>>>(h, DD, 0, W1 + (size_t)l * DD * DMLP, DMLP, 0,
                                         mlp, DMLP, 0,
                                         SS, DMLP, DD, 1.f, b1 + (size_t)l * DMLP, nullptr, 1, 0, 0);

        // x = x + mlp @ W2 + b2
        dim3 g2(DD / 128, SS / 128, 1);
        tgemm_kernel<false><<<g2, 256>>>(mlp, DMLP, 0, W2 + (size_t)l * DMLP * DD, DD, 0,
                                         x, DD, 0,
                                         SS, DD, DMLP, 1.f, b2 + (size_t)l * DD, x, 0, 0, 0);
    }

    layernorm_kernel<<<SS, 256>>>(x, lnfg, lnfb, h);

    // logits = h @ emb^T
    dim3 gl((NV + 127) / 128, SS / 128, 1);
    tgemm_kernel<true><<<gl, 256>>>(h, DD, 0, emb, DD, 0, out, NV, 0,
                                    SS, NV, DD, 1.f, nullptr, nullptr, 0, 0, 0);
}

// round 4
// speedup vs baseline: 4.1157x; 1.0192x over previous
#include <cuda_runtime.h>
#include <math.h>

#define SS   2048
#define DD   1024
#define NL   4
#define NH   16
#define HDIM 64
#define NV   50257
#define DMLP 4096

// ---------------- scratch ----------------
__device__ float g_x[SS * DD];
__device__ float g_h[SS * DD];
__device__ float g_q[SS * DD];
__device__ float g_k[SS * DD];
__device__ float g_v[SS * DD];
__device__ float g_mlp[SS * DMLP];
__device__ float g_scores[(size_t)NH * SS * SS];

// ---------------- embedding gather ----------------
__global__ void embed_kernel(const int* __restrict__ ids,
                             const float* __restrict__ emb,
                             float* __restrict__ x) {
    int t = blockIdx.x;
    int id = ids[t];
    if (id < 0) id = 0;
    if (id >= NV) id = NV - 1;
    const float* src = emb + (size_t)id * DD;
    float* dst = x + (size_t)t * DD;
    for (int d = threadIdx.x; d < DD; d += blockDim.x) dst[d] = src[d];
}

// ---------------- layernorm ----------------
__global__ void layernorm_kernel(const float* __restrict__ x,
                                 const float* __restrict__ g,
                                 const float* __restrict__ b,
                                 float* __restrict__ out) {
    __shared__ float red[256];
    int row = blockIdx.x;
    const float* xr = x + (size_t)row * DD;
    float s = 0.f;
    for (int d = threadIdx.x; d < DD; d += 256) s += xr[d];
    red[threadIdx.x] = s;
    __syncthreads();
    for (int o = 128; o > 0; o >>= 1) {
        if (threadIdx.x < o) red[threadIdx.x] += red[threadIdx.x + o];
        __syncthreads();
    }
    float mean = red[0] * (1.f / DD);
    __syncthreads();
    float v = 0.f;
    for (int d = threadIdx.x; d < DD; d += 256) {
        float t = xr[d] - mean;
        v += t * t;
    }
    red[threadIdx.x] = v;
    __syncthreads();
    for (int o = 128; o > 0; o >>= 1) {
        if (threadIdx.x < o) red[threadIdx.x] += red[threadIdx.x + o];
        __syncthreads();
    }
    float inv = rsqrtf(red[0] * (1.f / DD) + 1e-5f);
    float* orow = out + (size_t)row * DD;
    for (int d = threadIdx.x; d < DD; d += 256)
        orow[d] = (xr[d] - mean) * inv * g[d] + b[d];
}

// ---------------- RoPE ----------------
__global__ void rope_kernel(float* __restrict__ q, float* __restrict__ k) {
    int idx = blockIdx.x * blockDim.x + threadIdx.x;
    int i = idx & 31;
    int rest = idx >> 5;
    int h = rest & (NH - 1);
    int t = rest >> 4;
    if (t >= SS) return;
    float inv_freq = powf(10000.f, -(float)i / 32.f);
    float ang = (float)t * inv_freq;
    float c = cosf(ang), s = sinf(ang);
    size_t base = (size_t)t * DD + h * HDIM;
    float x1 = q[base + i], x2 = q[base + i + 32];
    q[base + i]      = x1 * c - x2 * s;
    q[base + i + 32] = x2 * c + x1 * s;
    float y1 = k[base + i], y2 = k[base + i + 32];
    k[base + i]      = y1 * c - y2 * s;
    k[base + i + 32] = y2 * c + y1 * s;
}

// ---------------- causal softmax ----------------
__global__ void softmax_kernel(float* __restrict__ scores) {
    __shared__ float red[256];
    int s = blockIdx.x, h = blockIdx.y;
    float* row = scores + ((size_t)h * SS + s) * SS;
    int valid = s + 1;
    float m = -1e30f;
    for (int j = threadIdx.x; j < valid; j += 256) m = fmaxf(m, row[j]);
    red[threadIdx.x] = m;
    __syncthreads();
    for (int o = 128; o > 0; o >>= 1) {
        if (threadIdx.x < o) red[threadIdx.x] = fmaxf(red[threadIdx.x], red[threadIdx.x + o]);
        __syncthreads();
    }
    m = red[0];
    __syncthreads();
    float sum = 0.f;
    for (int j = threadIdx.x; j < valid; j += 256) {
        float e = expf(row[j] - m);
        row[j] = e;
        sum += e;
    }
    red[threadIdx.x] = sum;
    __syncthreads();
    for (int o = 128; o > 0; o >>= 1) {
        if (threadIdx.x < o) red[threadIdx.x] += red[threadIdx.x + o];
        __syncthreads();
    }
    float invs = 1.f / red[0];
    for (int j = threadIdx.x; j < SS; j += 256)
        row[j] = (j < valid) ? row[j] * invs : 0.f;
}

// ================= TF32 tensor-core GEMM =================
// blockIdx.x = row-block, blockIdx.y = col-block (B-reuse ordering), z = batch.
#define BMT 128
#define BKT 16
#define APITCH 20

struct Ptr3 {
    const float* b0; const float* b1; const float* b2;
    float* c0; float* c1; float* c2;
};

__device__ __forceinline__ unsigned f2tf(float f) {
    unsigned u;
    asm("cvt.rna.tf32.f32 %0, %1;" : "=r"(u) : "f"(f));
    return u;
}

__device__ __forceinline__ void mma_tf32(float c[4], unsigned a0, unsigned a1,
                                         unsigned a2, unsigned a3,
                                         unsigned b0, unsigned b1) {
    asm volatile(
        "mma.sync.aligned.m16n8k8.row.col.f32.tf32.tf32.f32 "
        "{%0,%1,%2,%3}, {%4,%5,%6,%7}, {%8,%9}, {%0,%1,%2,%3};"
        : "+f"(c[0]), "+f"(c[1]), "+f"(c[2]), "+f"(c[3])
        : "r"(a0), "r"(a1), "r"(a2), "r"(a3), "r"(b0), "r"(b1));
}

template <int BN, bool TB>
__global__ void __launch_bounds__(256, 2)
tgemm_kernel(const float* __restrict__ A, int lda, long long strideA,
             Ptr3 p, int ldb, long long strideB,
             int ldc, long long strideC,
             int M, int N, int K, float alpha,
             const float* __restrict__ bias,
             const float* __restrict__ res,
             int do_gelu, int causal, int kcap, int multiB) {
    const int BPN = (BN == 128) ? 136 : 72;     // pitch for [k][n] B tiles
    const int BPT = 20;                          // pitch for [n][k] B tiles
    const int NBI = BN * BKT / 1024;             // float4 load iters for B
    const int MT  = (BN == 128) ? 4 : 2;

    __shared__ float As[2][BMT * APITCH];
    __shared__ float Bs[2][TB ? (BN * BPT) : (BKT * BPN)];

    int z = blockIdx.z;
    const float* B;
    float* C;
    if (multiB) {
        B = (z == 0) ? p.b0 : (z == 1) ? p.b1 : p.b2;
        C = (z == 0) ? p.c0 : (z == 1) ? p.c1 : p.c2;
    } else {
        B = p.b0 + (size_t)z * strideB;
        C = p.c0 + (size_t)z * strideC;
        if (res) res += (size_t)z * strideC;
    }
    A += (size_t)z * strideA;

    int row0 = blockIdx.x * BMT;
    int col0 = blockIdx.y * BN;
    if (causal && col0 >= row0 + BMT) return;

    int Keff = K;
    if (kcap) { int kc = row0 + BMT; Keff = (K < kc) ? K : kc; }
    int nk = Keff / BKT;

    int tid = threadIdx.x;
    int lane = tid & 31, warp = tid >> 5;
    int l4 = lane & 3, l28 = lane >> 2;
    int mbase, nbase;
    if (BN == 128) { mbase = (warp >> 2) * 64; nbase = (warp & 3) * 32; }
    else           { mbase = (warp >> 1) * 32; nbase = (warp & 1) * 32; }

    float acc[MT][4][4];
#pragma unroll
    for (int mt = 0; mt < MT; mt++)
#pragma unroll
        for (int nt = 0; nt < 4; nt++)
#pragma unroll
            for (int c = 0; c < 4; c++) acc[mt][nt][c] = 0.f;

    float4 ra[2], rb[NBI];

    // ---- global loads for stage s ----
    auto loadA = [&](int k0) {
#pragma unroll
        for (int i = 0; i < 2; i++) {
            int lin = i * 256 + tid;
            int m = lin >> 2, f4 = lin & 3;
            ra[i] = *(const float4*)(A + (size_t)(row0 + m) * lda + k0 + f4 * 4);
        }
    };
    auto loadB = [&](int k0) {
#pragma unroll
        for (int i = 0; i < NBI; i++) {
            int lin = i * 256 + tid;
            if (TB) {
                int n = lin >> 2, f4 = lin & 3;
                int gn = col0 + n;
                rb[i] = (gn < N) ? *(const float4*)(B + (size_t)gn * ldb + k0 + f4 * 4)
                                 : make_float4(0.f, 0.f, 0.f, 0.f);
            } else {
                int kk = lin / (BN / 4), f4 = lin % (BN / 4);
                int gn = col0 + f4 * 4;
                rb[i] = (gn < N) ? *(const float4*)(B + (size_t)(k0 + kk) * ldb + gn)
                                 : make_float4(0.f, 0.f, 0.f, 0.f);
            }
        }
    };
    auto storeStage = [&](int s) {
#pragma unroll
        for (int i = 0; i < 2; i++) {
            int lin = i * 256 + tid;
            int m = lin >> 2, f4 = lin & 3;
            float4 t;
            t.x = __uint_as_float(f2tf(ra[i].x));
            t.y = __uint_as_float(f2tf(ra[i].y));
            t.z = __uint_as_float(f2tf(ra[i].z));
            t.w = __uint_as_float(f2tf(ra[i].w));
            *(float4*)&As[s][m * APITCH + f4 * 4] = t;
        }
#pragma unroll
        for (int i = 0; i < NBI; i++) {
            int lin = i * 256 + tid;
            float4 t;
            t.x = __uint_as_float(f2tf(rb[i].x));
            t.y = __uint_as_float(f2tf(rb[i].y));
            t.z = __uint_as_float(f2tf(rb[i].z));
            t.w = __uint_as_float(f2tf(rb[i].w));
            if (TB) {
                int n = lin >> 2, f4 = lin & 3;
                *(float4*)&Bs[s][n * BPT + f4 * 4] = t;
            } else {
                int kk = lin / (BN / 4), f4 = lin % (BN / 4);
                *(float4*)&Bs[s][kk * BPN + f4 * 4] = t;
            }
        }
    };

    loadA(0);
    loadB(0);
    storeStage(0);
    __syncthreads();

    for (int ks = 0; ks < nk; ks++) {
        int cur = ks & 1, nxt = cur ^ 1;
        bool more = (ks + 1) < nk;
        if (more) {
            int k0 = (ks + 1) * BKT;
            loadA(k0);
            loadB(k0);
        }

#pragma unroll
        for (int kk8 = 0; kk8 < 2; kk8++) {
            int kb = kk8 * 8;
            unsigned af[MT][4];
#pragma unroll
            for (int mt = 0; mt < MT; mt++) {
                int mrow = mbase + mt * 16 + l28;
                af[mt][0] = __float_as_uint(As[cur][mrow * APITCH + kb + l4]);
                af[mt][1] = __float_as_uint(As[cur][(mrow + 8) * APITCH + kb + l4]);
                af[mt][2] = __float_as_uint(As[cur][mrow * APITCH + kb + l4 + 4]);
                af[mt][3] = __float_as_uint(As[cur][(mrow + 8) * APITCH + kb + l4 + 4]);
            }
            unsigned bf[4][2];
#pragma unroll
            for (int nt = 0; nt < 4; nt++) {
                int ncol = nbase + nt * 8 + l28;
                if (TB) {
                    bf[nt][0] = __float_as_uint(Bs[cur][ncol * BPT + kb + l4]);
                    bf[nt][1] = __float_as_uint(Bs[cur][ncol * BPT + kb + l4 + 4]);
                } else {
                    bf[nt][0] = __float_as_uint(Bs[cur][(kb + l4) * BPN + ncol]);
                    bf[nt][1] = __float_as_uint(Bs[cur][(kb + l4 + 4) * BPN + ncol]);
                }
            }
#pragma unroll
            for (int mt = 0; mt < MT; mt++)
#pragma unroll
                for (int nt = 0; nt < 4; nt++)
                    mma_tf32(acc[mt][nt], af[mt][0], af[mt][1], af[mt][2], af[mt][3],
                             bf[nt][0], bf[nt][1]);
        }

        if (more) storeStage(nxt);
        __syncthreads();
    }

    // ---- epilogue ----
#pragma unroll
    for (int mt = 0; mt < MT; mt++) {
#pragma unroll
        for (int nt = 0; nt < 4; nt++) {
#pragma unroll
            for (int c = 0; c < 4; c++) {
                int gr = row0 + mbase + mt * 16 + l28 + ((c >= 2) ? 8 : 0);
                int gc = col0 + nbase + nt * 8 + l4 * 2 + (c & 1);
                if (gc >= N) continue;
                float v = alpha * acc[mt][nt][c];
                if (bias) v += bias[gc];
                if (res) v += res[(size_t)gr * ldc + gc];
                if (do_gelu) v = 0.5f * v * (1.f + erff(v * 0.70710678118654752f));
                C[(size_t)gr * ldc + gc] = v;
            }
        }
    }
}

static inline Ptr3 one(const float* b, float* c) {
    Ptr3 p; p.b0 = b; p.b1 = nullptr; p.b2 = nullptr;
    p.c0 = c; p.c1 = nullptr; p.c2 = nullptr; return p;
}

// ---------------- host orchestration ----------------
extern "C" void kernel_launch(void* const* d_in, const int* in_sizes, int n_in,
                              void* d_out, int out_size) {
    const int*   ids  = (const int*)d_in[0];
    const float* emb  = (const float*)d_in[1];
    const float* Wq   = (const float*)d_in[2];
    const float* Wk   = (const float*)d_in[3];
    const float* Wv   = (const float*)d_in[4];
    const float* Wo   = (const float*)d_in[5];
    const float* ln1g = (const float*)d_in[6];
    const float* ln1b = (const float*)d_in[7];
    const float* ln2g = (const float*)d_in[8];
    const float* ln2b = (const float*)d_in[9];
    const float* W1   = (const float*)d_in[10];
    const float* b1   = (const float*)d_in[11];
    const float* W2   = (const float*)d_in[12];
    const float* b2   = (const float*)d_in[13];
    const float* lnfg = (const float*)d_in[14];
    const float* lnfb = (const float*)d_in[15];
    float* out = (float*)d_out;

    float *x, *h, *q, *k, *v, *mlp, *sc;
    cudaGetSymbolAddress((void**)&x,   g_x);
    cudaGetSymbolAddress((void**)&h,   g_h);
    cudaGetSymbolAddress((void**)&q,   g_q);
    cudaGetSymbolAddress((void**)&k,   g_k);
    cudaGetSymbolAddress((void**)&v,   g_v);
    cudaGetSymbolAddress((void**)&mlp, g_mlp);
    cudaGetSymbolAddress((void**)&sc,  g_scores);

    embed_kernel<<<SS, 256>>>(ids, emb, x);

    for (int l = 0; l < NL; l++) {
        const size_t wofs = (size_t)l * DD * DD;
        layernorm_kernel<<<SS, 256>>>(x, ln1g + l * DD, ln1b + l * DD, h);

        // fused QKV: z selects (W, out) pair
        {
            Ptr3 p;
            p.b0 = Wq + wofs; p.b1 = Wk + wofs; p.b2 = Wv + wofs;
            p.c0 = q; p.c1 = k; p.c2 = v;
            tgemm_kernel<128, false><<<dim3(SS / 128, DD / 128, 3), 256>>>(
                h, DD, 0, p, DD, 0, DD, 0,
                SS, DD, DD, 1.f, nullptr, nullptr, 0, 0, 0, 1);
        }

        rope_kernel<<<(SS * NH * 32 + 255) / 256, 256>>>(q, k);

        // scores[h] = 1/8 * q_h @ k_h^T (causal skip)
        tgemm_kernel<128, true><<<dim3(SS / 128, SS / 128, NH), 256>>>(
            q, DD, HDIM, one(k, sc), DD, HDIM, SS, (long long)SS * SS,
            SS, SS, HDIM, 0.125f, nullptr, nullptr, 0, 1, 0, 0);

        softmax_kernel<<<dim3(SS, NH), 256>>>(sc);

        // attn_out[h] = softmax @ v_h (BN=64, kcap)
        tgemm_kernel<64, false><<<dim3(SS / 128, 1, NH), 256>>>(
            sc, SS, (long long)SS * SS, one(v, h), DD, HDIM, DD, HDIM,
            SS, HDIM, SS, 1.f, nullptr, nullptr, 0, 0, 1, 0);

        // x = x + attn @ Wo  (BN=64)
        tgemm_kernel<64, false><<<dim3(SS / 128, DD / 64, 1), 256>>>(
            h, DD, 0, one(Wo + wofs, x), DD, 0, DD, 0,
            SS, DD, DD, 1.f, nullptr, x, 0, 0, 0, 0);

        layernorm_kernel<<<SS, 256>>>(x, ln2g + l * DD, ln2b + l * DD, h);

        // mlp = gelu(h @ W1 + b1)
        tgemm_kernel<128, false><<<dim3(SS / 128, DMLP / 128, 1), 256>>>(
            h, DD, 0, one(W1 + (size_t)l * DD * DMLP, mlp), DMLP, 0, DMLP, 0,
            SS, DMLP, DD, 1.f, b1 + (size_t)l * DMLP, nullptr, 1, 0, 0, 0);

        // x = x + mlp @ W2 + b2  (BN=64)
        tgemm_kernel<64, false><<<dim3(SS / 128, DD / 64, 1), 256>>>(
            mlp, DMLP, 0, one(W2 + (size_t)l * DMLP * DD, x), DD, 0, DD, 0,
            SS, DD, DMLP, 1.f, b2 + (size_t)l * DD, x, 0, 0, 0, 0);
    }

    layernorm_kernel<<<SS, 256>>>(x, lnfg, lnfb, h);

    // logits = h @ emb^T   (rows-fastest grid: emb streamed ~once)
    tgemm_kernel<128, true><<<dim3(SS / 128, (NV + 127) / 128, 1), 256>>>(
        h, DD, 0, one(emb, out), DD, 0, NV, 0,
        SS, NV, DD, 1.f, nullptr, nullptr, 0, 0, 0, 0);
}

// round 5
// speedup vs baseline: 5.0270x; 1.2214x over previous
#include <cuda_runtime.h>
#include <math.h>

#define SS   2048
#define DD   1024
#define NL   4
#define NH   16
#define HDIM 64
#define NV   50257
#define DMLP 4096

// ---------------- scratch ----------------
__device__ float g_x[SS * DD];
__device__ float g_h[SS * DD];
__device__ float g_q[SS * DD];
__device__ float g_k[SS * DD];
__device__ float g_v[SS * DD];
__device__ float g_mlp[SS * DMLP];
__device__ float g_scores[(size_t)NH * SS * SS];

// ---------------- embedding gather ----------------
__global__ void embed_kernel(const int* __restrict__ ids,
                             const float* __restrict__ emb,
                             float* __restrict__ x) {
    int t = blockIdx.x;
    int id = ids[t];
    if (id < 0) id = 0;
    if (id >= NV) id = NV - 1;
    const float* src = emb + (size_t)id * DD;
    float* dst = x + (size_t)t * DD;
    for (int d = threadIdx.x; d < DD; d += blockDim.x) dst[d] = src[d];
}

// ---------------- layernorm ----------------
__global__ void layernorm_kernel(const float* __restrict__ x,
                                 const float* __restrict__ g,
                                 const float* __restrict__ b,
                                 float* __restrict__ out) {
    __shared__ float red[256];
    int row = blockIdx.x;
    const float* xr = x + (size_t)row * DD;
    float s = 0.f;
    for (int d = threadIdx.x; d < DD; d += 256) s += xr[d];
    red[threadIdx.x] = s;
    __syncthreads();
    for (int o = 128; o > 0; o >>= 1) {
        if (threadIdx.x < o) red[threadIdx.x] += red[threadIdx.x + o];
        __syncthreads();
    }
    float mean = red[0] * (1.f / DD);
    __syncthreads();
    float v = 0.f;
    for (int d = threadIdx.x; d < DD; d += 256) {
        float t = xr[d] - mean;
        v += t * t;
    }
    red[threadIdx.x] = v;
    __syncthreads();
    for (int o = 128; o > 0; o >>= 1) {
        if (threadIdx.x < o) red[threadIdx.x] += red[threadIdx.x + o];
        __syncthreads();
    }
    float inv = rsqrtf(red[0] * (1.f / DD) + 1e-5f);
    float* orow = out + (size_t)row * DD;
    for (int d = threadIdx.x; d < DD; d += 256)
        orow[d] = (xr[d] - mean) * inv * g[d] + b[d];
}

// ---------------- RoPE ----------------
__global__ void rope_kernel(float* __restrict__ q, float* __restrict__ k) {
    int idx = blockIdx.x * blockDim.x + threadIdx.x;
    int i = idx & 31;
    int rest = idx >> 5;
    int h = rest & (NH - 1);
    int t = rest >> 4;
    if (t >= SS) return;
    float inv_freq = powf(10000.f, -(float)i / 32.f);
    float ang = (float)t * inv_freq;
    float c = cosf(ang), s = sinf(ang);
    size_t base = (size_t)t * DD + h * HDIM;
    float x1 = q[base + i], x2 = q[base + i + 32];
    q[base + i]      = x1 * c - x2 * s;
    q[base + i + 32] = x2 * c + x1 * s;
    float y1 = k[base + i], y2 = k[base + i + 32];
    k[base + i]      = y1 * c - y2 * s;
    k[base + i + 32] = y2 * c + y1 * s;
}

// ---------------- causal softmax ----------------
__global__ void softmax_kernel(float* __restrict__ scores) {
    __shared__ float red[256];
    int s = blockIdx.x, h = blockIdx.y;
    float* row = scores + ((size_t)h * SS + s) * SS;
    int valid = s + 1;
    float m = -1e30f;
    for (int j = threadIdx.x; j < valid; j += 256) m = fmaxf(m, row[j]);
    red[threadIdx.x] = m;
    __syncthreads();
    for (int o = 128; o > 0; o >>= 1) {
        if (threadIdx.x < o) red[threadIdx.x] = fmaxf(red[threadIdx.x], red[threadIdx.x + o]);
        __syncthreads();
    }
    m = red[0];
    __syncthreads();
    float sum = 0.f;
    for (int j = threadIdx.x; j < valid; j += 256) {
        float e = expf(row[j] - m);
        row[j] = e;
        sum += e;
    }
    red[threadIdx.x] = sum;
    __syncthreads();
    for (int o = 128; o > 0; o >>= 1) {
        if (threadIdx.x < o) red[threadIdx.x] += red[threadIdx.x + o];
        __syncthreads();
    }
    float invs = 1.f / red[0];
    for (int j = threadIdx.x; j < SS; j += 256)
        row[j] = (j < valid) ? row[j] * invs : 0.f;
}

// ================= TF32 tensor-core GEMM, cp.async pipeline =================
#define BMT 128
#define BKT 16
#define APITCH 20

struct Ptr3 {
    const float* b0; const float* b1; const float* b2;
    float* c0; float* c1; float* c2;
};

__device__ __forceinline__ unsigned f2tf(float f) {
    unsigned u;
    asm("cvt.rna.tf32.f32 %0, %1;" : "=r"(u) : "f"(f));
    return u;
}

__device__ __forceinline__ void cp16(unsigned dst, const void* src, int bytes) {
    asm volatile("cp.async.cg.shared.global [%0], [%1], 16, %2;"
                 :: "r"(dst), "l"(src), "r"(bytes));
}
__device__ __forceinline__ void cp_commit() {
    asm volatile("cp.async.commit_group;");
}
template <int N>
__device__ __forceinline__ void cp_wait() {
    asm volatile("cp.async.wait_group %0;" :: "n"(N));
}

__device__ __forceinline__ void mma_tf32(float c[4], unsigned a0, unsigned a1,
                                         unsigned a2, unsigned a3,
                                         unsigned b0, unsigned b1) {
    asm volatile(
        "mma.sync.aligned.m16n8k8.row.col.f32.tf32.tf32.f32 "
        "{%0,%1,%2,%3}, {%4,%5,%6,%7}, {%8,%9}, {%0,%1,%2,%3};"
        : "+f"(c[0]), "+f"(c[1]), "+f"(c[2]), "+f"(c[3])
        : "r"(a0), "r"(a1), "r"(a2), "r"(a3), "r"(b0), "r"(b1));
}

template <int BN, bool TB>
__global__ void __launch_bounds__(256, 2)
tgemm_kernel(const float* __restrict__ A, int lda, long long strideA,
             Ptr3 p, int ldb, long long strideB,
             int ldc, long long strideC,
             int M, int N, int K, float alpha,
             const float* __restrict__ bias,
             const float* __restrict__ res,
             int do_gelu, int causal, int kcap, int multiB) {
    const int BPN = (BN == 128) ? 136 : 72;    // [k][n] pitch
    const int BPT = 20;                         // [n][k] pitch
    const int NBI = (BN * BKT) / 1024;          // float4 iters for B (2 or 1)
    const int MT  = (BN == 128) ? 4 : 2;

    __shared__ __align__(16) float As[2][BMT * APITCH];
    __shared__ __align__(16) float Bs[2][TB ? (BN * BPT) : (BKT * BPN)];

    int z = blockIdx.z;
    const float* B;
    float* C;
    if (multiB) {
        B = (z == 0) ? p.b0 : (z == 1) ? p.b1 : p.b2;
        C = (z == 0) ? p.c0 : (z == 1) ? p.c1 : p.c2;
    } else {
        B = p.b0 + (size_t)z * strideB;
        C = p.c0 + (size_t)z * strideC;
        if (res) res += (size_t)z * strideC;
    }
    A += (size_t)z * strideA;

    int row0 = blockIdx.x * BMT;
    int col0 = blockIdx.y * BN;
    if (causal && col0 >= row0 + BMT) return;

    int Keff = K;
    if (kcap) { int kc = row0 + BMT; Keff = (K < kc) ? K : kc; }
    int nk = Keff / BKT;

    int tid = threadIdx.x;
    int lane = tid & 31, warp = tid >> 5;
    int l4 = lane & 3, l28 = lane >> 2;
    int mbase, nbase;
    if (BN == 128) { mbase = (warp >> 2) * 64; nbase = (warp & 3) * 32; }
    else           { mbase = (warp >> 1) * 32; nbase = (warp & 1) * 32; }

    unsigned sA[2], sB[2];
    sA[0] = (unsigned)__cvta_generic_to_shared(&As[0][0]);
    sA[1] = (unsigned)__cvta_generic_to_shared(&As[1][0]);
    sB[0] = (unsigned)__cvta_generic_to_shared(&Bs[0][0]);
    sB[1] = (unsigned)__cvta_generic_to_shared(&Bs[1][0]);

    float acc[MT][4][4];
#pragma unroll
    for (int mt = 0; mt < MT; mt++)
#pragma unroll
        for (int nt = 0; nt < 4; nt++)
#pragma unroll
            for (int c = 0; c < 4; c++) acc[mt][nt][c] = 0.f;

    // ---- async tile loads (raw fp32 into smem) ----
    auto prefetch = [&](int s, int k0) {
#pragma unroll
        for (int i = 0; i < 2; i++) {
            int lin = i * 256 + tid;
            int m = lin >> 2, f4 = lin & 3;
            cp16(sA[s] + (m * APITCH + f4 * 4) * 4,
                 A + (size_t)(row0 + m) * lda + k0 + f4 * 4, 16);
        }
#pragma unroll
        for (int i = 0; i < NBI; i++) {
            int lin = i * 256 + tid;
            if (TB) {
                int n = lin >> 2, f4 = lin & 3;
                int gn = col0 + n;
                cp16(sB[s] + (n * BPT + f4 * 4) * 4,
                     B + (size_t)gn * ldb + k0 + f4 * 4, (gn < N) ? 16 : 0);
            } else {
                int kk = lin / (BN / 4), f4 = lin % (BN / 4);
                cp16(sB[s] + (kk * BPN + f4 * 4) * 4,
                     B + (size_t)(k0 + kk) * ldb + col0 + f4 * 4, 16);
            }
        }
        cp_commit();
    };

    prefetch(0, 0);

    for (int ks = 0; ks < nk; ks++) {
        int cur = ks & 1, nxt = cur ^ 1;
        bool more = (ks + 1) < nk;
        if (more) prefetch(nxt, (ks + 1) * BKT);

        if (more) cp_wait<1>(); else cp_wait<0>();
        __syncthreads();

#pragma unroll
        for (int kk8 = 0; kk8 < 2; kk8++) {
            int kb = kk8 * 8;
            unsigned af[MT][4];
#pragma unroll
            for (int mt = 0; mt < MT; mt++) {
                int mrow = mbase + mt * 16 + l28;
                af[mt][0] = f2tf(As[cur][mrow * APITCH + kb + l4]);
                af[mt][1] = f2tf(As[cur][(mrow + 8) * APITCH + kb + l4]);
                af[mt][2] = f2tf(As[cur][mrow * APITCH + kb + l4 + 4]);
                af[mt][3] = f2tf(As[cur][(mrow + 8) * APITCH + kb + l4 + 4]);
            }
            unsigned bf[4][2];
#pragma unroll
            for (int nt = 0; nt < 4; nt++) {
                int ncol = nbase + nt * 8 + l28;
                if (TB) {
                    bf[nt][0] = f2tf(Bs[cur][ncol * BPT + kb + l4]);
                    bf[nt][1] = f2tf(Bs[cur][ncol * BPT + kb + l4 + 4]);
                } else {
                    bf[nt][0] = f2tf(Bs[cur][(kb + l4) * BPN + ncol]);
                    bf[nt][1] = f2tf(Bs[cur][(kb + l4 + 4) * BPN + ncol]);
                }
            }
#pragma unroll
            for (int mt = 0; mt < MT; mt++)
#pragma unroll
                for (int nt = 0; nt < 4; nt++)
                    mma_tf32(acc[mt][nt], af[mt][0], af[mt][1], af[mt][2], af[mt][3],
                             bf[nt][0], bf[nt][1]);
        }
        __syncthreads();
    }

    // ---- epilogue ----
#pragma unroll
    for (int mt = 0; mt < MT; mt++) {
#pragma unroll
        for (int nt = 0; nt < 4; nt++) {
#pragma unroll
            for (int c = 0; c < 4; c++) {
                int gr = row0 + mbase + mt * 16 + l28 + ((c >= 2) ? 8 : 0);
                int gc = col0 + nbase + nt * 8 + l4 * 2 + (c & 1);
                if (gc >= N) continue;
                float v = alpha * acc[mt][nt][c];
                if (bias) v += bias[gc];
                if (res) v += res[(size_t)gr * ldc + gc];
                if (do_gelu) v = 0.5f * v * (1.f + erff(v * 0.70710678118654752f));
                C[(size_t)gr * ldc + gc] = v;
            }
        }
    }
}

static inline Ptr3 one(const float* b, float* c) {
    Ptr3 p; p.b0 = b; p.b1 = nullptr; p.b2 = nullptr;
    p.c0 = c; p.c1 = nullptr; p.c2 = nullptr; return p;
}

// ---------------- host orchestration ----------------
extern "C" void kernel_launch(void* const* d_in, const int* in_sizes, int n_in,
                              void* d_out, int out_size) {
    const int*   ids  = (const int*)d_in[0];
    const float* emb  = (const float*)d_in[1];
    const float* Wq   = (const float*)d_in[2];
    const float* Wk   = (const float*)d_in[3];
    const float* Wv   = (const float*)d_in[4];
    const float* Wo   = (const float*)d_in[5];
    const float* ln1g = (const float*)d_in[6];
    const float* ln1b = (const float*)d_in[7];
    const float* ln2g = (const float*)d_in[8];
    const float* ln2b = (const float*)d_in[9];
    const float* W1   = (const float*)d_in[10];
    const float* b1   = (const float*)d_in[11];
    const float* W2   = (const float*)d_in[12];
    const float* b2   = (const float*)d_in[13];
    const float* lnfg = (const float*)d_in[14];
    const float* lnfb = (const float*)d_in[15];
    float* out = (float*)d_out;

    float *x, *h, *q, *k, *v, *mlp, *sc;
    cudaGetSymbolAddress((void**)&x,   g_x);
    cudaGetSymbolAddress((void**)&h,   g_h);
    cudaGetSymbolAddress((void**)&q,   g_q);
    cudaGetSymbolAddress((void**)&k,   g_k);
    cudaGetSymbolAddress((void**)&v,   g_v);
    cudaGetSymbolAddress((void**)&mlp, g_mlp);
    cudaGetSymbolAddress((void**)&sc,  g_scores);

    embed_kernel<<<SS, 256>>>(ids, emb, x);

    for (int l = 0; l < NL; l++) {
        const size_t wofs = (size_t)l * DD * DD;
        layernorm_kernel<<<SS, 256>>>(x, ln1g + l * DD, ln1b + l * DD, h);

        // fused QKV
        {
            Ptr3 p;
            p.b0 = Wq + wofs; p.b1 = Wk + wofs; p.b2 = Wv + wofs;
            p.c0 = q; p.c1 = k; p.c2 = v;
            tgemm_kernel<128, false><<<dim3(SS / 128, DD / 128, 3), 256>>>(
                h, DD, 0, p, DD, 0, DD, 0,
                SS, DD, DD, 1.f, nullptr, nullptr, 0, 0, 0, 1);
        }

        rope_kernel<<<(SS * NH * 32 + 255) / 256, 256>>>(q, k);

        // scores = 1/8 q k^T (causal skip)
        tgemm_kernel<128, true><<<dim3(SS / 128, SS / 128, NH), 256>>>(
            q, DD, HDIM, one(k, sc), DD, HDIM, SS, (long long)SS * SS,
            SS, SS, HDIM, 0.125f, nullptr, nullptr, 0, 1, 0, 0);

        softmax_kernel<<<dim3(SS, NH), 256>>>(sc);

        // attn_out = softmax @ v (BN=64, kcap)
        tgemm_kernel<64, false><<<dim3(SS / 128, 1, NH), 256>>>(
            sc, SS, (long long)SS * SS, one(v, h), DD, HDIM, DD, HDIM,
            SS, HDIM, SS, 1.f, nullptr, nullptr, 0, 0, 1, 0);

        // x = x + attn @ Wo (BN=64)
        tgemm_kernel<64, false><<<dim3(SS / 128, DD / 64, 1), 256>>>(
            h, DD, 0, one(Wo + wofs, x), DD, 0, DD, 0,
            SS, DD, DD, 1.f, nullptr, x, 0, 0, 0, 0);

        layernorm_kernel<<<SS, 256>>>(x, ln2g + l * DD, ln2b + l * DD, h);

        // mlp = gelu(h @ W1 + b1)
        tgemm_kernel<128, false><<<dim3(SS / 128, DMLP / 128, 1), 256>>>(
            h, DD, 0, one(W1 + (size_t)l * DD * DMLP, mlp), DMLP, 0, DMLP, 0,
            SS, DMLP, DD, 1.f, b1 + (size_t)l * DMLP, nullptr, 1, 0, 0, 0);

        // x = x + mlp @ W2 + b2 (BN=64)
        tgemm_kernel<64, false><<<dim3(SS / 128, DD / 64, 1), 256>>>(
            mlp, DMLP, 0, one(W2 + (size_t)l * DMLP * DD, x), DD, 0, DD, 0,
            SS, DD, DMLP, 1.f, b2 + (size_t)l * DD, x, 0, 0, 0, 0);
    }

    layernorm_kernel<<<SS, 256>>>(x, lnfg, lnfb, h);

    // logits = h @ emb^T (row-blocks fastest: emb col-block reused across x-dim)
    tgemm_kernel<128, true><<<dim3(SS / 128, (NV + 127) / 128, 1), 256>>>(
        h, DD, 0, one(emb, out), DD, 0, NV, 0,
        SS, NV, DD, 1.f, nullptr, nullptr, 0, 0, 0, 0);
}

// round 7
// speedup vs baseline: 5.6799x; 1.1299x over previous
#include <cuda_runtime.h>
#include <math.h>
#include <stdint.h>

#define SS   2048
#define DD   1024
#define NL   4
#define NH   16
#define HDIM 64
#define NV   50257
#define DMLP 4096

// ---------------- scratch ----------------
__device__ float g_x[SS * DD];
__device__ float g_h[SS * DD];
__device__ float g_q[SS * DD];
__device__ float g_k[SS * DD];
__device__ float g_v[SS * DD];
__device__ float g_mlp[SS * DMLP];

// ---------------- embedding gather ----------------
__global__ void embed_kernel(const int* __restrict__ ids,
                             const float* __restrict__ emb,
                             float* __restrict__ x) {
    int t = blockIdx.x;
    int id = ids[t];
    if (id < 0) id = 0;
    if (id >= NV) id = NV - 1;
    const float* src = emb + (size_t)id * DD;
    float* dst = x + (size_t)t * DD;
    for (int d = threadIdx.x; d < DD; d += blockDim.x) dst[d] = src[d];
}

// ---------------- layernorm ----------------
__global__ void layernorm_kernel(const float* __restrict__ x,
                                 const float* __restrict__ g,
                                 const float* __restrict__ b,
                                 float* __restrict__ out) {
    __shared__ float red[256];
    int row = blockIdx.x;
    const float* xr = x + (size_t)row * DD;
    float s = 0.f;
    for (int d = threadIdx.x; d < DD; d += 256) s += xr[d];
    red[threadIdx.x] = s;
    __syncthreads();
    for (int o = 128; o > 0; o >>= 1) {
        if (threadIdx.x < o) red[threadIdx.x] += red[threadIdx.x + o];
        __syncthreads();
    }
    float mean = red[0] * (1.f / DD);
    __syncthreads();
    float v = 0.f;
    for (int d = threadIdx.x; d < DD; d += 256) {
        float t = xr[d] - mean;
        v += t * t;
    }
    red[threadIdx.x] = v;
    __syncthreads();
    for (int o = 128; o > 0; o >>= 1) {
        if (threadIdx.x < o) red[threadIdx.x] += red[threadIdx.x + o];
        __syncthreads();
    }
    float inv = rsqrtf(red[0] * (1.f / DD) + 1e-5f);
    float* orow = out + (size_t)row * DD;
    for (int d = threadIdx.x; d < DD; d += 256)
        orow[d] = (xr[d] - mean) * inv * g[d] + b[d];
}

// ---------------- RoPE ----------------
__global__ void rope_kernel(float* __restrict__ q, float* __restrict__ k) {
    int idx = blockIdx.x * blockDim.x + threadIdx.x;
    int i = idx & 31;
    int rest = idx >> 5;
    int h = rest & (NH - 1);
    int t = rest >> 4;
    if (t >= SS) return;
    float inv_freq = powf(10000.f, -(float)i / 32.f);
    float ang = (float)t * inv_freq;
    float c = cosf(ang), s = sinf(ang);
    size_t base = (size_t)t * DD + h * HDIM;
    float x1 = q[base + i], x2 = q[base + i + 32];
    q[base + i]      = x1 * c - x2 * s;
    q[base + i + 32] = x2 * c + x1 * s;
    float y1 = k[base + i], y2 = k[base + i + 32];
    k[base + i]      = y1 * c - y2 * s;
    k[base + i + 32] = y2 * c + y1 * s;
}

// ---------------- common PTX helpers ----------------
__device__ __forceinline__ unsigned f2tf(float f) {
    unsigned u;
    asm("cvt.rna.tf32.f32 %0, %1;" : "=r"(u) : "f"(f));
    return u;
}
__device__ __forceinline__ void cp16(unsigned dst, const void* src, int bytes) {
    asm volatile("cp.async.cg.shared.global [%0], [%1], 16, %2;"
                 :: "r"(dst), "l"(src), "r"(bytes));
}
__device__ __forceinline__ void cp_commit() {
    asm volatile("cp.async.commit_group;");
}
template <int N>
__device__ __forceinline__ void cp_wait() {
    asm volatile("cp.async.wait_group %0;" :: "n"(N));
}
__device__ __forceinline__ void mma_tf32(float c[4], unsigned a0, unsigned a1,
                                         unsigned a2, unsigned a3,
                                         unsigned b0, unsigned b1) {
    asm volatile(
        "mma.sync.aligned.m16n8k8.row.col.f32.tf32.tf32.f32 "
        "{%0,%1,%2,%3}, {%4,%5,%6,%7}, {%8,%9}, {%0,%1,%2,%3};"
        : "+f"(c[0]), "+f"(c[1]), "+f"(c[2]), "+f"(c[3])
        : "r"(a0), "r"(a1), "r"(a2), "r"(a3), "r"(b0), "r"(b1));
}

// ================= TF32 mma.sync GEMM (R5, proven) =================
#define BMT 128
#define BKT 16
#define APITCH 20

struct Ptr3 {
    const float* b0; const float* b1; const float* b2;
    float* c0; float* c1; float* c2;
};

template <int BN, bool TB>
__global__ void __launch_bounds__(256, 2)
tgemm_kernel(const float* __restrict__ A, int lda, long long strideA,
             Ptr3 p, int ldb, long long strideB,
             int ldc, long long strideC,
             int M, int N, int K, float alpha,
             const float* __restrict__ bias,
             const float* __restrict__ res,
             int do_gelu, int multiB) {
    const int BPN = (BN == 128) ? 136 : 72;
    const int BPT = 20;
    const int NBI = (BN * BKT) / 1024;
    const int MT  = (BN == 128) ? 4 : 2;

    __shared__ __align__(16) float As[2][BMT * APITCH];
    __shared__ __align__(16) float Bs[2][TB ? (BN * BPT) : (BKT * BPN)];

    int z = blockIdx.z;
    const float* B;
    float* C;
    if (multiB) {
        B = (z == 0) ? p.b0 : (z == 1) ? p.b1 : p.b2;
        C = (z == 0) ? p.c0 : (z == 1) ? p.c1 : p.c2;
    } else {
        B = p.b0 + (size_t)z * strideB;
        C = p.c0 + (size_t)z * strideC;
        if (res) res += (size_t)z * strideC;
    }
    A += (size_t)z * strideA;

    int row0 = blockIdx.x * BMT;
    int col0 = blockIdx.y * BN;
    int nk = K / BKT;

    int tid = threadIdx.x;
    int lane = tid & 31, warp = tid >> 5;
    int l4 = lane & 3, l28 = lane >> 2;
    int mbase, nbase;
    if (BN == 128) { mbase = (warp >> 2) * 64; nbase = (warp & 3) * 32; }
    else           { mbase = (warp >> 1) * 32; nbase = (warp & 1) * 32; }

    unsigned sA[2], sB[2];
    sA[0] = (unsigned)__cvta_generic_to_shared(&As[0][0]);
    sA[1] = (unsigned)__cvta_generic_to_shared(&As[1][0]);
    sB[0] = (unsigned)__cvta_generic_to_shared(&Bs[0][0]);
    sB[1] = (unsigned)__cvta_generic_to_shared(&Bs[1][0]);

    float acc[MT][4][4];
#pragma unroll
    for (int mt = 0; mt < MT; mt++)
#pragma unroll
        for (int nt = 0; nt < 4; nt++)
#pragma unroll
            for (int c = 0; c < 4; c++) acc[mt][nt][c] = 0.f;

    auto prefetch = [&](int s, int k0) {
#pragma unroll
        for (int i = 0; i < 2; i++) {
            int lin = i * 256 + tid;
            int m = lin >> 2, f4 = lin & 3;
            cp16(sA[s] + (m * APITCH + f4 * 4) * 4,
                 A + (size_t)(row0 + m) * lda + k0 + f4 * 4, 16);
        }
#pragma unroll
        for (int i = 0; i < NBI; i++) {
            int lin = i * 256 + tid;
            if (TB) {
                int n = lin >> 2, f4 = lin & 3;
                int gn = col0 + n;
                cp16(sB[s] + (n * BPT + f4 * 4) * 4,
                     B + (size_t)gn * ldb + k0 + f4 * 4, (gn < N) ? 16 : 0);
            } else {
                int kk = lin / (BN / 4), f4 = lin % (BN / 4);
                cp16(sB[s] + (kk * BPN + f4 * 4) * 4,
                     B + (size_t)(k0 + kk) * ldb + col0 + f4 * 4, 16);
            }
        }
        cp_commit();
    };

    prefetch(0, 0);

    for (int ks = 0; ks < nk; ks++) {
        int cur = ks & 1, nxt = cur ^ 1;
        bool more = (ks + 1) < nk;
        if (more) prefetch(nxt, (ks + 1) * BKT);

        if (more) cp_wait<1>(); else cp_wait<0>();
        __syncthreads();

#pragma unroll
        for (int kk8 = 0; kk8 < 2; kk8++) {
            int kb = kk8 * 8;
            unsigned af[MT][4];
#pragma unroll
            for (int mt = 0; mt < MT; mt++) {
                int mrow = mbase + mt * 16 + l28;
                af[mt][0] = f2tf(As[cur][mrow * APITCH + kb + l4]);
                af[mt][1] = f2tf(As[cur][(mrow + 8) * APITCH + kb + l4]);
                af[mt][2] = f2tf(As[cur][mrow * APITCH + kb + l4 + 4]);
                af[mt][3] = f2tf(As[cur][(mrow + 8) * APITCH + kb + l4 + 4]);
            }
            unsigned bf[4][2];
#pragma unroll
            for (int nt = 0; nt < 4; nt++) {
                int ncol = nbase + nt * 8 + l28;
                if (TB) {
                    bf[nt][0] = f2tf(Bs[cur][ncol * BPT + kb + l4]);
                    bf[nt][1] = f2tf(Bs[cur][ncol * BPT + kb + l4 + 4]);
                } else {
                    bf[nt][0] = f2tf(Bs[cur][(kb + l4) * BPN + ncol]);
                    bf[nt][1] = f2tf(Bs[cur][(kb + l4 + 4) * BPN + ncol]);
                }
            }
#pragma unroll
            for (int mt = 0; mt < MT; mt++)
#pragma unroll
                for (int nt = 0; nt < 4; nt++)
                    mma_tf32(acc[mt][nt], af[mt][0], af[mt][1], af[mt][2], af[mt][3],
                             bf[nt][0], bf[nt][1]);
        }
        __syncthreads();
    }

#pragma unroll
    for (int mt = 0; mt < MT; mt++) {
#pragma unroll
        for (int nt = 0; nt < 4; nt++) {
#pragma unroll
            for (int c = 0; c < 4; c++) {
                int gr = row0 + mbase + mt * 16 + l28 + ((c >= 2) ? 8 : 0);
                int gc = col0 + nbase + nt * 8 + l4 * 2 + (c & 1);
                if (gc >= N) continue;
                float v = alpha * acc[mt][nt][c];
                if (bias) v += bias[gc];
                if (res) v += res[(size_t)gr * ldc + gc];
                if (do_gelu) v = 0.5f * v * (1.f + erff(v * 0.70710678118654752f));
                C[(size_t)gr * ldc + gc] = v;
            }
        }
    }
}

static inline Ptr3 one(const float* b, float* c) {
    Ptr3 p; p.b0 = b; p.b1 = nullptr; p.b2 = nullptr;
    p.c0 = c; p.c1 = nullptr; p.c2 = nullptr; return p;
}

// ================= fused causal flash attention (tf32 mma.sync) =================
// grid (16 rowblocks, 16 heads), 256 thr. CTA handles 128 q-rows of one head.
// Q frags in regs (scale folded), K/V tiles double-buffered via cp.async.
#define FKP 68    // K smem pitch (floats), %32==4 -> conflict-free [n][k] frags
#define FVP 72    // V smem pitch (floats), %32==8 -> conflict-free [k][n] frags
#define FA_SMEM ((2 * 128 * FKP + 2 * 128 * FVP) * 4)

__global__ void __launch_bounds__(256, 1)
flash_kernel(const float* __restrict__ q, const float* __restrict__ k,
             const float* __restrict__ v, float* __restrict__ o) {
    extern __shared__ __align__(16) float fsm[];
    float* Ksm[2] = { fsm, fsm + 128 * FKP };
    float* Vsm[2] = { fsm + 2 * 128 * FKP, fsm + 2 * 128 * FKP + 128 * FVP };
    unsigned uK[2], uV[2];
    uK[0] = (unsigned)__cvta_generic_to_shared(Ksm[0]);
    uK[1] = (unsigned)__cvta_generic_to_shared(Ksm[1]);
    uV[0] = (unsigned)__cvta_generic_to_shared(Vsm[0]);
    uV[1] = (unsigned)__cvta_generic_to_shared(Vsm[1]);

    int rb = 15 - blockIdx.x;          // heavy row-blocks scheduled first
    int hb = blockIdx.y * HDIM;
    int row0 = rb * 128;

    int tid = threadIdx.x, lane = tid & 31, w = tid >> 5;
    int l4 = lane & 3, l28 = lane >> 2;
    int rl0 = w * 16 + l28;            // local rows of this thread
    int rl1 = rl0 + 8;
    int grow0 = row0 + rl0, grow1 = row0 + rl1;

    // Q fragments, scale 1/8 folded (exact: exponent shift), tf32 once.
    unsigned qa[8][4];
#pragma unroll
    for (int c = 0; c < 8; c++) {
        qa[c][0] = f2tf(0.125f * q[(size_t)grow0 * DD + hb + 8 * c + l4]);
        qa[c][1] = f2tf(0.125f * q[(size_t)grow1 * DD + hb + 8 * c + l4]);
        qa[c][2] = f2tf(0.125f * q[(size_t)grow0 * DD + hb + 8 * c + l4 + 4]);
        qa[c][3] = f2tf(0.125f * q[(size_t)grow1 * DD + hb + 8 * c + l4 + 4]);
    }

    float oacc[8][4];
#pragma unroll
    for (int n2 = 0; n2 < 8; n2++)
#pragma unroll
        for (int c = 0; c < 4; c++) oacc[n2][c] = 0.f;
    float mA = -1e30f, mB = -1e30f, lA = 0.f, lB = 0.f;

    auto prefetch = [&](int j, int s) {
#pragma unroll
        for (int i = 0; i < 8; i++) {
            int lin = i * 256 + tid;
            int r = lin >> 4, f4 = lin & 15;
            const float* gk = k + (size_t)(j * 128 + r) * DD + hb + f4 * 4;
            const float* gv = v + (size_t)(j * 128 + r) * DD + hb + f4 * 4;
            cp16(uK[s] + (r * FKP + f4 * 4) * 4, gk, 16);
            cp16(uV[s] + (r * FVP + f4 * 4) * 4, gv, 16);
        }
        cp_commit();
    };

    int src0 = (lane & ~3) | (l4 >> 1);
    int src1 = src0 + 2;
    bool par = (l4 & 1) != 0;

    prefetch(0, 0);

    for (int j = 0; j <= rb; j++) {
        int s = j & 1;
        bool more = j < rb;
        if (more) prefetch(j + 1, s ^ 1);
        if (more) cp_wait<1>(); else cp_wait<0>();
        __syncthreads();

        // ---- S = (Q/8) @ K^T : 16 n-tiles of 8 kv-cols ----
        float sacc[16][4];
#pragma unroll
        for (int t = 0; t < 16; t++)
#pragma unroll
            for (int c = 0; c < 4; c++) sacc[t][c] = 0.f;
#pragma unroll
        for (int c = 0; c < 8; c++) {
#pragma unroll
            for (int t = 0; t < 16; t++) {
                unsigned b0 = f2tf(Ksm[s][(t * 8 + l28) * FKP + 8 * c + l4]);
                unsigned b1 = f2tf(Ksm[s][(t * 8 + l28) * FKP + 8 * c + l4 + 4]);
                mma_tf32(sacc[t], qa[c][0], qa[c][1], qa[c][2], qa[c][3], b0, b1);
            }
        }

        // ---- causal mask on diagonal tile ----
        if (j == rb) {
#pragma unroll
            for (int t = 0; t < 16; t++) {
                int cb = 8 * t + 2 * l4;
                if (cb     > rl0) sacc[t][0] = -1e30f;
                if (cb + 1 > rl0) sacc[t][1] = -1e30f;
                if (cb     > rl1) sacc[t][2] = -1e30f;
                if (cb + 1 > rl1) sacc[t][3] = -1e30f;
            }
        }

        // ---- online softmax ----
        float tmA = -1e30f, tmB = -1e30f;
#pragma unroll
        for (int t = 0; t < 16; t++) {
            tmA = fmaxf(tmA, fmaxf(sacc[t][0], sacc[t][1]));
            tmB = fmaxf(tmB, fmaxf(sacc[t][2], sacc[t][3]));
        }
        tmA = fmaxf(tmA, __shfl_xor_sync(0xffffffffu, tmA, 1));
        tmA = fmaxf(tmA, __shfl_xor_sync(0xffffffffu, tmA, 2));
        tmB = fmaxf(tmB, __shfl_xor_sync(0xffffffffu, tmB, 1));
        tmB = fmaxf(tmB, __shfl_xor_sync(0xffffffffu, tmB, 2));

        float mnA = fmaxf(mA, tmA), mnB = fmaxf(mB, tmB);
        float cA = __expf(mA - mnA), cB = __expf(mB - mnB);
        mA = mnA; mB = mnB;

        float tsA = 0.f, tsB = 0.f;
#pragma unroll
        for (int t = 0; t < 16; t++) {
            sacc[t][0] = __expf(sacc[t][0] - mA);
            sacc[t][1] = __expf(sacc[t][1] - mA);
            sacc[t][2] = __expf(sacc[t][2] - mB);
            sacc[t][3] = __expf(sacc[t][3] - mB);
            tsA += sacc[t][0] + sacc[t][1];
            tsB += sacc[t][2] + sacc[t][3];
        }
        tsA += __shfl_xor_sync(0xffffffffu, tsA, 1);
        tsA += __shfl_xor_sync(0xffffffffu, tsA, 2);
        tsB += __shfl_xor_sync(0xffffffffu, tsB, 1);
        tsB += __shfl_xor_sync(0xffffffffu, tsB, 2);
        lA = lA * cA + tsA;
        lB = lB * cB + tsB;

#pragma unroll
        for (int n2 = 0; n2 < 8; n2++) {
            oacc[n2][0] *= cA; oacc[n2][1] *= cA;
            oacc[n2][2] *= cB; oacc[n2][3] *= cB;
        }

        // ---- O += P @ V : accum->A-operand via quad shfl ----
#pragma unroll
        for (int kc = 0; kc < 16; kc++) {
            float v00 = __shfl_sync(0xffffffffu, sacc[kc][0], src0);
            float v01 = __shfl_sync(0xffffffffu, sacc[kc][1], src0);
            float v10 = __shfl_sync(0xffffffffu, sacc[kc][2], src0);
            float v11 = __shfl_sync(0xffffffffu, sacc[kc][3], src0);
            float w00 = __shfl_sync(0xffffffffu, sacc[kc][0], src1);
            float w01 = __shfl_sync(0xffffffffu, sacc[kc][1], src1);
            float w10 = __shfl_sync(0xffffffffu, sacc[kc][2], src1);
            float w11 = __shfl_sync(0xffffffffu, sacc[kc][3], src1);
            unsigned a0 = f2tf(par ? v01 : v00);
            unsigned a1 = f2tf(par ? v11 : v10);
            unsigned a2 = f2tf(par ? w01 : w00);
            unsigned a3 = f2tf(par ? w11 : w10);
#pragma unroll
            for (int n2 = 0; n2 < 8; n2++) {
                unsigned b0 = f2tf(Vsm[s][(kc * 8 + l4) * FVP + n2 * 8 + l28]);
                unsigned b1 = f2tf(Vsm[s][(kc * 8 + l4 + 4) * FVP + n2 * 8 + l28]);
                mma_tf32(oacc[n2], a0, a1, a2, a3, b0, b1);
            }
        }
        __syncthreads();
    }

    float iA = 1.f / lA, iB = 1.f / lB;
#pragma unroll
    for (int n2 = 0; n2 < 8; n2++) {
        *(float2*)&o[(size_t)grow0 * DD + hb + n2 * 8 + 2 * l4] =
            make_float2(oacc[n2][0] * iA, oacc[n2][1] * iA);
        *(float2*)&o[(size_t)grow1 * DD + hb + n2 * 8 + 2 * l4] =
            make_float2(oacc[n2][2] * iB, oacc[n2][3] * iB);
    }
}

// ---------------- host orchestration ----------------
extern "C" void kernel_launch(void* const* d_in, const int* in_sizes, int n_in,
                              void* d_out, int out_size) {
    const int*   ids  = (const int*)d_in[0];
    const float* emb  = (const float*)d_in[1];
    const float* Wq   = (const float*)d_in[2];
    const float* Wk   = (const float*)d_in[3];
    const float* Wv   = (const float*)d_in[4];
    const float* Wo   = (const float*)d_in[5];
    const float* ln1g = (const float*)d_in[6];
    const float* ln1b = (const float*)d_in[7];
    const float* ln2g = (const float*)d_in[8];
    const float* ln2b = (const float*)d_in[9];
    const float* W1   = (const float*)d_in[10];
    const float* b1   = (const float*)d_in[11];
    const float* W2   = (const float*)d_in[12];
    const float* b2   = (const float*)d_in[13];
    const float* lnfg = (const float*)d_in[14];
    const float* lnfb = (const float*)d_in[15];
    float* out = (float*)d_out;

    float *x, *h, *q, *k, *v, *mlp;
    cudaGetSymbolAddress((void**)&x,   g_x);
    cudaGetSymbolAddress((void**)&h,   g_h);
    cudaGetSymbolAddress((void**)&q,   g_q);
    cudaGetSymbolAddress((void**)&k,   g_k);
    cudaGetSymbolAddress((void**)&v,   g_v);
    cudaGetSymbolAddress((void**)&mlp, g_mlp);

    cudaFuncSetAttribute(flash_kernel,
                         cudaFuncAttributeMaxDynamicSharedMemorySize, FA_SMEM);

    embed_kernel<<<SS, 256>>>(ids, emb, x);

    for (int l = 0; l < NL; l++) {
        const size_t wofs = (size_t)l * DD * DD;
        layernorm_kernel<<<SS, 256>>>(x, ln1g + l * DD, ln1b + l * DD, h);

        // fused QKV
        {
            Ptr3 p;
            p.b0 = Wq + wofs; p.b1 = Wk + wofs; p.b2 = Wv + wofs;
            p.c0 = q; p.c1 = k; p.c2 = v;
            tgemm_kernel<128, false><<<dim3(SS / 128, DD / 128, 3), 256>>>(
                h, DD, 0, p, DD, 0, DD, 0,
                SS, DD, DD, 1.f, nullptr, nullptr, 0, 1);
        }

        rope_kernel<<<(SS * NH * 32 + 255) / 256, 256>>>(q, k);

        // fused causal attention -> h
        flash_kernel<<<dim3(SS / 128, NH), 256, FA_SMEM>>>(q, k, v, h);

        // x = x + attn @ Wo
        tgemm_kernel<64, false><<<dim3(SS / 128, DD / 64, 1), 256>>>(
            h, DD, 0, one(Wo + wofs, x), DD, 0, DD, 0,
            SS, DD, DD, 1.f, nullptr, x, 0, 0);

        layernorm_kernel<<<SS, 256>>>(x, ln2g + l * DD, ln2b + l * DD, h);

        // mlp = gelu(h @ W1 + b1)
        tgemm_kernel<128, false><<<dim3(SS / 128, DMLP / 128, 1), 256>>>(
            h, DD, 0, one(W1 + (size_t)l * DD * DMLP, mlp), DMLP, 0, DMLP, 0,
            SS, DMLP, DD, 1.f, b1 + (size_t)l * DMLP, nullptr, 1, 0);

        // x = x + mlp @ W2 + b2
        tgemm_kernel<64, false><<<dim3(SS / 128, DD / 64, 1), 256>>>(
            mlp, DMLP, 0, one(W2 + (size_t)l * DMLP * DD, x), DD, 0, DD, 0,
            SS, DD, DMLP, 1.f, b2 + (size_t)l * DD, x, 0, 0);
    }

    layernorm_kernel<<<SS, 256>>>(x, lnfg, lnfb, h);

    // logits = h @ emb^T (tf32; row-blocks fastest for emb reuse)
    tgemm_kernel<128, true><<<dim3(SS / 128, (NV + 127) / 128, 1), 256>>>(
        h, DD, 0, one(emb, out), DD, 0, NV, 0,
        SS, NV, DD, 1.f, nullptr, nullptr, 0, 0);
}